// round 2
// baseline (speedup 1.0000x reference)
#include <cuda_runtime.h>
#include <math.h>

#define BT 32768      // B*T = 32*1024
#define D  512
#define NMOD 3

// Scratch (allocation-free rule: __device__ globals)
__device__ float g_fused[(size_t)NMOD * BT * D];  // fused states, [i, token, d]
__device__ float g_p[(size_t)NMOD * BT * D];      // projection result (pre-bias)

// ---------------------------------------------------------------------------
// Kernel 1: per-token cosine sims -> softmax weights -> fused states.
// One warp per token. Each lane holds 16 floats (4 x float4) per modality.
// ---------------------------------------------------------------------------
__global__ void fusion_kernel(const float* __restrict__ s0,
                              const float* __restrict__ s1,
                              const float* __restrict__ s2,
                              float* __restrict__ weights_out) {
    int gwarp = (blockIdx.x * blockDim.x + threadIdx.x) >> 5;
    int lane  = threadIdx.x & 31;
    if (gwarp >= BT) return;

    const float4* p0 = (const float4*)(s0 + (size_t)gwarp * D);
    const float4* p1 = (const float4*)(s1 + (size_t)gwarp * D);
    const float4* p2 = (const float4*)(s2 + (size_t)gwarp * D);

    float4 v0[4], v1[4], v2[4];
#pragma unroll
    for (int q = 0; q < 4; q++) {
        v0[q] = p0[lane + q * 32];
        v1[q] = p1[lane + q * 32];
        v2[q] = p2[lane + q * 32];
    }

    // Partial dot products: d00,d11,d22,d01,d02,d12
    float d[6] = {0.f, 0.f, 0.f, 0.f, 0.f, 0.f};
#pragma unroll
    for (int q = 0; q < 4; q++) {
        float4 a = v0[q], b = v1[q], c = v2[q];
        d[0] += a.x * a.x + a.y * a.y + a.z * a.z + a.w * a.w;
        d[1] += b.x * b.x + b.y * b.y + b.z * b.z + b.w * b.w;
        d[2] += c.x * c.x + c.y * c.y + c.z * c.z + c.w * c.w;
        d[3] += a.x * b.x + a.y * b.y + a.z * b.z + a.w * b.w;
        d[4] += a.x * c.x + a.y * c.y + a.z * c.z + a.w * c.w;
        d[5] += b.x * c.x + b.y * c.y + b.z * c.z + b.w * c.w;
    }
#pragma unroll
    for (int t = 0; t < 6; t++) {
#pragma unroll
        for (int off = 16; off > 0; off >>= 1)
            d[t] += __shfl_xor_sync(0xffffffffu, d[t], off);
    }

    float n0 = sqrtf(d[0]), n1 = sqrtf(d[1]), n2 = sqrtf(d[2]);

    // sims[i][j] = dots / max(n_i*n_j, 1e-8) / 0.5
    float sim[3][3];
    sim[0][0] = d[0] / fmaxf(n0 * n0, 1e-8f) * 2.0f;
    sim[1][1] = d[1] / fmaxf(n1 * n1, 1e-8f) * 2.0f;
    sim[2][2] = d[2] / fmaxf(n2 * n2, 1e-8f) * 2.0f;
    float s01 = d[3] / fmaxf(n0 * n1, 1e-8f) * 2.0f;
    float s02 = d[4] / fmaxf(n0 * n2, 1e-8f) * 2.0f;
    float s12 = d[5] / fmaxf(n1 * n2, 1e-8f) * 2.0f;
    sim[0][1] = s01; sim[1][0] = s01;
    sim[0][2] = s02; sim[2][0] = s02;
    sim[1][2] = s12; sim[2][1] = s12;

    // softmax over j (3 states) for each core i
    float w[3][3];
#pragma unroll
    for (int i = 0; i < 3; i++) {
        float m  = fmaxf(sim[i][0], fmaxf(sim[i][1], sim[i][2]));
        float e0 = expf(sim[i][0] - m);
        float e1 = expf(sim[i][1] - m);
        float e2 = expf(sim[i][2] - m);
        float inv = 1.0f / (e0 + e1 + e2);
        w[i][0] = e0 * inv; w[i][1] = e1 * inv; w[i][2] = e2 * inv;
    }

    // weights output: [i, b, t, j]
    if (lane < 9) {
        int i = lane / 3, j = lane % 3;
        weights_out[((size_t)i * BT + gwarp) * 3 + j] = w[i][j];
    }

    // fused[i] = sum_j w[i][j] * S[j]
#pragma unroll
    for (int i = 0; i < 3; i++) {
        float4* dst = (float4*)(g_fused + ((size_t)i * BT + gwarp) * D);
        float w0 = w[i][0], w1 = w[i][1], w2 = w[i][2];
#pragma unroll
        for (int q = 0; q < 4; q++) {
            float4 r;
            r.x = w0 * v0[q].x + w1 * v1[q].x + w2 * v2[q].x;
            r.y = w0 * v0[q].y + w1 * v1[q].y + w2 * v2[q].y;
            r.z = w0 * v0[q].z + w1 * v1[q].z + w2 * v2[q].z;
            r.w = w0 * v0[q].w + w1 * v1[q].w + w2 * v2[q].w;
            dst[lane + q * 32] = r;
        }
    }
}

// ---------------------------------------------------------------------------
// Kernel 2: fp32 tiled GEMM. C[i] = fused[i] (M x K) @ W[i]^T, W[i] is [N,K].
// Block tile 128x128, BK=16, 256 threads, 8x8 per-thread microtile.
// ---------------------------------------------------------------------------
#define GBM 128
#define GBN 128
#define GBK 16

__global__ void __launch_bounds__(256, 2)
gemm_kernel(const float* __restrict__ proj_w) {
    const int mod = blockIdx.z;
    const float* A = g_fused + (size_t)mod * BT * D;       // [BT, D]
    const float* W = proj_w + (size_t)mod * D * D;          // [N=D, K=D]
    float* C = g_p + (size_t)mod * BT * D;

    __shared__ float As[GBK][GBM];
    __shared__ float Bs[GBK][GBN];

    const int tid = threadIdx.x;
    const int m0 = blockIdx.y * GBM;
    const int n0 = blockIdx.x * GBN;
    const int ty = tid >> 4;       // 0..15
    const int tx = tid & 15;       // 0..15

    float acc[8][8];
#pragma unroll
    for (int r = 0; r < 8; r++)
#pragma unroll
        for (int c = 0; c < 8; c++) acc[r][c] = 0.f;

    for (int k0 = 0; k0 < D; k0 += GBK) {
#pragma unroll
        for (int it = 0; it < 2; it++) {
            int idx = tid + it * 256;       // 0..511 (128 rows x 4 float4-cols)
            int row = idx >> 2;
            int c4  = (idx & 3) << 2;
            float4 va = *(const float4*)(A + (size_t)(m0 + row) * D + k0 + c4);
            As[c4 + 0][row] = va.x; As[c4 + 1][row] = va.y;
            As[c4 + 2][row] = va.z; As[c4 + 3][row] = va.w;
            float4 vb = *(const float4*)(W + (size_t)(n0 + row) * D + k0 + c4);
            Bs[c4 + 0][row] = vb.x; Bs[c4 + 1][row] = vb.y;
            Bs[c4 + 2][row] = vb.z; Bs[c4 + 3][row] = vb.w;
        }
        __syncthreads();

#pragma unroll
        for (int k = 0; k < GBK; k++) {
            float a[8], b[8];
            *(float4*)&a[0] = *(const float4*)&As[k][ty * 8];
            *(float4*)&a[4] = *(const float4*)&As[k][ty * 8 + 4];
            *(float4*)&b[0] = *(const float4*)&Bs[k][tx * 8];
            *(float4*)&b[4] = *(const float4*)&Bs[k][tx * 8 + 4];
#pragma unroll
            for (int r = 0; r < 8; r++)
#pragma unroll
                for (int c = 0; c < 8; c++)
                    acc[r][c] += a[r] * b[c];
        }
        __syncthreads();
    }

#pragma unroll
    for (int r = 0; r < 8; r++) {
        float* dst = C + (size_t)(m0 + ty * 8 + r) * D + n0 + tx * 8;
        *(float4*)dst       = make_float4(acc[r][0], acc[r][1], acc[r][2], acc[r][3]);
        *(float4*)(dst + 4) = make_float4(acc[r][4], acc[r][5], acc[r][6], acc[r][7]);
    }
}

// ---------------------------------------------------------------------------
// Kernel 3: x = S + (p + proj_b); LayerNorm over D; write out.
// One warp per row (3*BT rows).
// ---------------------------------------------------------------------------
__global__ void ln_kernel(const float* __restrict__ s0,
                          const float* __restrict__ s1,
                          const float* __restrict__ s2,
                          const float* __restrict__ proj_b,
                          const float* __restrict__ ln_g,
                          const float* __restrict__ ln_b,
                          float* __restrict__ out) {
    int row  = (blockIdx.x * blockDim.x + threadIdx.x) >> 5;
    int lane = threadIdx.x & 31;
    if (row >= NMOD * BT) return;
    int i   = row / BT;
    int tok = row - i * BT;

    const float* sbase = (i == 0) ? s0 : ((i == 1) ? s1 : s2);
    const float4* sp = (const float4*)(sbase + (size_t)tok * D);
    const float4* pp = (const float4*)(g_p + (size_t)row * D);
    const float4* bb = (const float4*)(proj_b + (size_t)i * D);

    float4 x[4];
    float sum = 0.f, sumsq = 0.f;
#pragma unroll
    for (int q = 0; q < 4; q++) {
        float4 a = sp[lane + q * 32];
        float4 c = pp[lane + q * 32];
        float4 b = bb[lane + q * 32];
        x[q].x = a.x + c.x + b.x;
        x[q].y = a.y + c.y + b.y;
        x[q].z = a.z + c.z + b.z;
        x[q].w = a.w + c.w + b.w;
        sum   += x[q].x + x[q].y + x[q].z + x[q].w;
        sumsq += x[q].x * x[q].x + x[q].y * x[q].y + x[q].z * x[q].z + x[q].w * x[q].w;
    }
#pragma unroll
    for (int off = 16; off > 0; off >>= 1) {
        sum   += __shfl_xor_sync(0xffffffffu, sum, off);
        sumsq += __shfl_xor_sync(0xffffffffu, sumsq, off);
    }
    float mu   = sum * (1.0f / D);
    float var  = sumsq * (1.0f / D) - mu * mu;
    float rstd = rsqrtf(var + 1e-5f);

    const float4* gg = (const float4*)(ln_g + (size_t)i * D);
    const float4* be = (const float4*)(ln_b + (size_t)i * D);
    float4* op = (float4*)(out + (size_t)row * D);
#pragma unroll
    for (int q = 0; q < 4; q++) {
        float4 g = gg[lane + q * 32];
        float4 b = be[lane + q * 32];
        float4 r;
        r.x = (x[q].x - mu) * rstd * g.x + b.x;
        r.y = (x[q].y - mu) * rstd * g.y + b.y;
        r.z = (x[q].z - mu) * rstd * g.z + b.z;
        r.w = (x[q].w - mu) * rstd * g.w + b.w;
        op[lane + q * 32] = r;
    }
}

// ---------------------------------------------------------------------------
extern "C" void kernel_launch(void* const* d_in, const int* in_sizes, int n_in,
                              void* d_out, int out_size) {
    const float* s0 = (const float*)d_in[0];   // s_flow [32,1024,512]
    const float* s1 = (const float*)d_in[1];   // s_wave
    const float* s2 = (const float*)d_in[2];   // s_wind
    const float* pw = (const float*)d_in[3];   // proj_w [3,512,512]
    const float* pb = (const float*)d_in[4];   // proj_b [3,512]
    const float* lg = (const float*)d_in[5];   // ln_g   [3,512]
    const float* lb = (const float*)d_in[6];   // ln_b   [3,512]

    float* out     = (float*)d_out;                    // [3,B,T,D]
    float* weights = out + (size_t)NMOD * BT * D;      // [3,B,T,3]

    // Stage 1: fusion weights + fused states (1 warp/token, 8 warps/block)
    fusion_kernel<<<BT / 8, 256>>>(s0, s1, s2, weights);

    // Stage 2: 3 projection GEMMs
    dim3 ggrid(D / GBN, BT / GBM, NMOD);   // (4, 256, 3)
    gemm_kernel<<<ggrid, 256>>>(pw);

    // Stage 3: residual + bias + LayerNorm
    ln_kernel<<<(NMOD * BT) / 8, 256>>>(s0, s1, s2, pb, lg, lb, out);
}

// round 5
// speedup vs baseline: 3.4801x; 3.4801x over previous
#include <cuda_runtime.h>
#include <cuda_bf16.h>
#include <math.h>
#include <stdint.h>

#define BT 32768      // B*T
#define D  512
#define NMOD 3

// ---------------------------------------------------------------------------
// Scratch (__device__ globals; allocation-free rule)
// ---------------------------------------------------------------------------
__device__ __align__(16) __nv_bfloat16 g_fa_hi[(size_t)NMOD * BT * D];
__device__ __align__(16) __nv_bfloat16 g_fa_lo[(size_t)NMOD * BT * D];
__device__ __align__(16) __nv_bfloat16 g_wb_hi[(size_t)NMOD * D * D];
__device__ __align__(16) __nv_bfloat16 g_wb_lo[(size_t)NMOD * D * D];
__device__ __align__(16) float g_p[(size_t)NMOD * BT * D];   // projection result

// ---------------------------------------------------------------------------
// helpers
// ---------------------------------------------------------------------------
__device__ __forceinline__ uint32_t smem_to_u32(const void* p) {
    uint32_t a;
    asm("{ .reg .u64 t; cvta.to.shared.u64 t, %1; cvt.u32.u64 %0, t; }" : "=r"(a) : "l"(p));
    return a;
}
__device__ __forceinline__ void cp16(uint32_t s, const void* g) {
    asm volatile("cp.async.cg.shared.global [%0], [%1], 16;" :: "r"(s), "l"(g) : "memory");
}
__device__ __forceinline__ void ldsm4(uint32_t* r, uint32_t addr) {
    asm volatile("ldmatrix.sync.aligned.m8n8.x4.shared.b16 {%0,%1,%2,%3}, [%4];"
                 : "=r"(r[0]), "=r"(r[1]), "=r"(r[2]), "=r"(r[3]) : "r"(addr));
}
__device__ __forceinline__ void mma16816(float* c, const uint32_t* a, const uint32_t* b) {
    asm volatile("mma.sync.aligned.m16n8k16.row.col.f32.bf16.bf16.f32 "
                 "{%0,%1,%2,%3}, {%4,%5,%6,%7}, {%8,%9}, {%0,%1,%2,%3};"
                 : "+f"(c[0]), "+f"(c[1]), "+f"(c[2]), "+f"(c[3])
                 : "r"(a[0]), "r"(a[1]), "r"(a[2]), "r"(a[3]), "r"(b[0]), "r"(b[1]));
}

__device__ __forceinline__ void split4(float4 v, uint2& hi, uint2& lo) {
    __nv_bfloat16 hx = __float2bfloat16(v.x);
    __nv_bfloat16 hy = __float2bfloat16(v.y);
    __nv_bfloat16 hz = __float2bfloat16(v.z);
    __nv_bfloat16 hw = __float2bfloat16(v.w);
    __nv_bfloat16 lx = __float2bfloat16(v.x - __bfloat162float(hx));
    __nv_bfloat16 ly = __float2bfloat16(v.y - __bfloat162float(hy));
    __nv_bfloat16 lz = __float2bfloat16(v.z - __bfloat162float(hz));
    __nv_bfloat16 lw = __float2bfloat16(v.w - __bfloat162float(hw));
    __nv_bfloat162 h01 = __halves2bfloat162(hx, hy);
    __nv_bfloat162 h23 = __halves2bfloat162(hz, hw);
    __nv_bfloat162 l01 = __halves2bfloat162(lx, ly);
    __nv_bfloat162 l23 = __halves2bfloat162(lz, lw);
    hi.x = *(uint32_t*)&h01; hi.y = *(uint32_t*)&h23;
    lo.x = *(uint32_t*)&l01; lo.y = *(uint32_t*)&l23;
}

// ---------------------------------------------------------------------------
// Kernel 1: fusion -> softmax weights + fused states (bf16 hi/lo)
// ---------------------------------------------------------------------------
__global__ void fusion_kernel(const float* __restrict__ s0,
                              const float* __restrict__ s1,
                              const float* __restrict__ s2,
                              float* __restrict__ weights_out) {
    int gwarp = (blockIdx.x * blockDim.x + threadIdx.x) >> 5;
    int lane  = threadIdx.x & 31;
    if (gwarp >= BT) return;

    const float4* p0 = (const float4*)(s0 + (size_t)gwarp * D);
    const float4* p1 = (const float4*)(s1 + (size_t)gwarp * D);
    const float4* p2 = (const float4*)(s2 + (size_t)gwarp * D);

    float4 v0[4], v1[4], v2[4];
#pragma unroll
    for (int q = 0; q < 4; q++) {
        v0[q] = p0[lane + q * 32];
        v1[q] = p1[lane + q * 32];
        v2[q] = p2[lane + q * 32];
    }
    float d[6] = {0.f, 0.f, 0.f, 0.f, 0.f, 0.f};
#pragma unroll
    for (int q = 0; q < 4; q++) {
        float4 a = v0[q], b = v1[q], c = v2[q];
        d[0] += a.x * a.x + a.y * a.y + a.z * a.z + a.w * a.w;
        d[1] += b.x * b.x + b.y * b.y + b.z * b.z + b.w * b.w;
        d[2] += c.x * c.x + c.y * c.y + c.z * c.z + c.w * c.w;
        d[3] += a.x * b.x + a.y * b.y + a.z * b.z + a.w * b.w;
        d[4] += a.x * c.x + a.y * c.y + a.z * c.z + a.w * c.w;
        d[5] += b.x * c.x + b.y * c.y + b.z * c.z + b.w * c.w;
    }
#pragma unroll
    for (int t = 0; t < 6; t++)
#pragma unroll
        for (int off = 16; off > 0; off >>= 1)
            d[t] += __shfl_xor_sync(0xffffffffu, d[t], off);

    float n0 = sqrtf(d[0]), n1 = sqrtf(d[1]), n2 = sqrtf(d[2]);
    float sim[3][3];
    sim[0][0] = d[0] / fmaxf(n0 * n0, 1e-8f) * 2.0f;
    sim[1][1] = d[1] / fmaxf(n1 * n1, 1e-8f) * 2.0f;
    sim[2][2] = d[2] / fmaxf(n2 * n2, 1e-8f) * 2.0f;
    float s01 = d[3] / fmaxf(n0 * n1, 1e-8f) * 2.0f;
    float s02 = d[4] / fmaxf(n0 * n2, 1e-8f) * 2.0f;
    float s12 = d[5] / fmaxf(n1 * n2, 1e-8f) * 2.0f;
    sim[0][1] = s01; sim[1][0] = s01;
    sim[0][2] = s02; sim[2][0] = s02;
    sim[1][2] = s12; sim[2][1] = s12;

    float w[3][3];
#pragma unroll
    for (int i = 0; i < 3; i++) {
        float m  = fmaxf(sim[i][0], fmaxf(sim[i][1], sim[i][2]));
        float e0 = expf(sim[i][0] - m);
        float e1 = expf(sim[i][1] - m);
        float e2 = expf(sim[i][2] - m);
        float inv = 1.0f / (e0 + e1 + e2);
        w[i][0] = e0 * inv; w[i][1] = e1 * inv; w[i][2] = e2 * inv;
    }
    if (lane < 9) {
        int i = lane / 3, j = lane % 3;
        weights_out[((size_t)i * BT + gwarp) * 3 + j] = w[i][j];
    }
#pragma unroll
    for (int i = 0; i < 3; i++) {
        uint2* dhi = (uint2*)(g_fa_hi + ((size_t)i * BT + gwarp) * D);
        uint2* dlo = (uint2*)(g_fa_lo + ((size_t)i * BT + gwarp) * D);
        float w0 = w[i][0], w1 = w[i][1], w2 = w[i][2];
#pragma unroll
        for (int q = 0; q < 4; q++) {
            float4 r;
            r.x = w0 * v0[q].x + w1 * v1[q].x + w2 * v2[q].x;
            r.y = w0 * v0[q].y + w1 * v1[q].y + w2 * v2[q].y;
            r.z = w0 * v0[q].z + w1 * v1[q].z + w2 * v2[q].z;
            r.w = w0 * v0[q].w + w1 * v1[q].w + w2 * v2[q].w;
            uint2 hi, lo;
            split4(r, hi, lo);
            dhi[lane + q * 32] = hi;
            dlo[lane + q * 32] = lo;
        }
    }
}

// ---------------------------------------------------------------------------
// Kernel 1b: convert proj_w (fp32) -> bf16 hi/lo
// ---------------------------------------------------------------------------
__global__ void wconv_kernel(const float* __restrict__ pw) {
    int idx = blockIdx.x * blockDim.x + threadIdx.x;
    const int total = NMOD * D * D / 4;
    if (idx >= total) return;
    float4 v = ((const float4*)pw)[idx];
    uint2 hi, lo;
    split4(v, hi, lo);
    ((uint2*)g_wb_hi)[idx] = hi;
    ((uint2*)g_wb_lo)[idx] = lo;
}

// ---------------------------------------------------------------------------
// Kernel 2: bf16 mma.sync GEMM, 3-pass hi/lo split, fp32 accum.
// C[i] = fused[i] @ W[i]^T, CTA tile 128x128, warp tile 32x64, K chunk 32,
// double-buffered cp.async. SMEM rows padded to 40 bf16 (80B) ->
// ldmatrix phase-conflict-free.
// ---------------------------------------------------------------------------
#define CHUNK_B   40960              // one buffer: 4 arrays * 128 rows * 80B
#define AHI_OFF   0
#define ALO_OFF   10240
#define BHI_OFF   20480
#define BLO_OFF   30720
#define GEMM_SMEM (2 * CHUNK_B)      // 81920

__global__ void __launch_bounds__(256, 2)
gemm_kernel() {
    extern __shared__ char sm[];
    const uint32_t smb = smem_to_u32(sm);
    const int tid  = threadIdx.x;
    const int wid  = tid >> 5;
    const int lane = tid & 31;
    const int n0   = blockIdx.x * 128;
    const int m0   = blockIdx.y * 128;
    const int mod  = blockIdx.z;

    const int wr = wid & 3;        // warp row (32 m-rows each)
    const int wc = wid >> 2;       // warp col (64 n-cols each)

    const uint4* gah = (const uint4*)(g_fa_hi + (size_t)mod * BT * D);
    const uint4* gal = (const uint4*)(g_fa_lo + (size_t)mod * BT * D);
    const uint4* gbh = (const uint4*)(g_wb_hi + (size_t)mod * D * D);
    const uint4* gbl = (const uint4*)(g_wb_lo + (size_t)mod * D * D);
    // global row stride = 512 bf16 = 64 uint4

    // loader lambda: chunk ch (k0 = ch*32) into buffer buf
    auto load_chunk = [&](int ch, int buf) {
        const uint32_t bb = smb + buf * CHUNK_B;
#pragma unroll
        for (int it = 0; it < 2; it++) {
            int idx = tid + it * 256;        // 0..511
            int row = idx >> 2;              // 0..127
            int pc  = idx & 3;               // 16B piece
            uint32_t so = bb + row * 80 + pc * 16;
            size_t ga = (size_t)(m0 + row) * 64 + ch * 4 + pc;
            size_t gb = (size_t)(n0 + row) * 64 + ch * 4 + pc;
            cp16(so + AHI_OFF, gah + ga);
            cp16(so + ALO_OFF, gal + ga);
            cp16(so + BHI_OFF, gbh + gb);
            cp16(so + BLO_OFF, gbl + gb);
        }
        asm volatile("cp.async.commit_group;" ::: "memory");
    };

    float acc[2][8][4];
#pragma unroll
    for (int mt = 0; mt < 2; mt++)
#pragma unroll
        for (int nt = 0; nt < 8; nt++)
#pragma unroll
            for (int q = 0; q < 4; q++) acc[mt][nt][q] = 0.f;

    // ldmatrix lane addressing (constant across chunks)
    const uint32_t a_row = wr * 32 + (lane & 15);            // + mt*16
    const uint32_t a_col = (lane >> 4) << 3;                 // + kk
    const uint32_t b_row = wc * 64 + (((lane >> 4) << 3) | (lane & 7));  // + np*16
    const uint32_t b_col = ((lane >> 3) & 1) << 3;           // + kk

    load_chunk(0, 0);

    for (int ch = 0; ch < 16; ch++) {
        if (ch < 15) load_chunk(ch + 1, (ch + 1) & 1);
        if (ch < 15) { asm volatile("cp.async.wait_group 1;" ::: "memory"); }
        else         { asm volatile("cp.async.wait_group 0;" ::: "memory"); }
        __syncthreads();

        const uint32_t bb = smb + (ch & 1) * CHUNK_B;
#pragma unroll
        for (int pass = 0; pass < 3; pass++) {
            const uint32_t abase = bb + ((pass == 2) ? ALO_OFF : AHI_OFF);
            const uint32_t bbase = bb + ((pass == 1) ? BLO_OFF : BHI_OFF);
#pragma unroll
            for (int kk2 = 0; kk2 < 2; kk2++) {
                const uint32_t kk = kk2 * 16;
                uint32_t a[2][4];
#pragma unroll
                for (int mt = 0; mt < 2; mt++)
                    ldsm4(a[mt], abase + (a_row + mt * 16) * 80 + (a_col + kk) * 2);
                uint32_t b[4][4];
#pragma unroll
                for (int np = 0; np < 4; np++)
                    ldsm4(b[np], bbase + (b_row + np * 16) * 80 + (b_col + kk) * 2);
#pragma unroll
                for (int mt = 0; mt < 2; mt++)
#pragma unroll
                    for (int nt = 0; nt < 8; nt++)
                        mma16816(acc[mt][nt], a[mt], &b[nt >> 1][(nt & 1) * 2]);
            }
        }
        __syncthreads();
    }

    // epilogue: write C tile to g_p
    float* Cp = g_p + (size_t)mod * BT * D;
    const int gid = lane >> 2, tq = lane & 3;
#pragma unroll
    for (int mt = 0; mt < 2; mt++) {
        const int r0 = m0 + wr * 32 + mt * 16 + gid;
#pragma unroll
        for (int nt = 0; nt < 8; nt++) {
            const int c = n0 + wc * 64 + nt * 8 + tq * 2;
            *(float2*)(Cp + (size_t)r0 * D + c)       = make_float2(acc[mt][nt][0], acc[mt][nt][1]);
            *(float2*)(Cp + (size_t)(r0 + 8) * D + c) = make_float2(acc[mt][nt][2], acc[mt][nt][3]);
        }
    }
}

// ---------------------------------------------------------------------------
// Kernel 3: x = S + (p + proj_b); LayerNorm over D; write out.
// ---------------------------------------------------------------------------
__global__ void ln_kernel(const float* __restrict__ s0,
                          const float* __restrict__ s1,
                          const float* __restrict__ s2,
                          const float* __restrict__ proj_b,
                          const float* __restrict__ ln_g,
                          const float* __restrict__ ln_b,
                          float* __restrict__ out) {
    int row  = (blockIdx.x * blockDim.x + threadIdx.x) >> 5;
    int lane = threadIdx.x & 31;
    if (row >= NMOD * BT) return;
    int i   = row / BT;
    int tok = row - i * BT;

    const float* sbase = (i == 0) ? s0 : ((i == 1) ? s1 : s2);
    const float4* sp = (const float4*)(sbase + (size_t)tok * D);
    const float4* pp = (const float4*)(g_p + (size_t)row * D);
    const float4* bb = (const float4*)(proj_b + (size_t)i * D);

    float4 x[4];
    float sum = 0.f, sumsq = 0.f;
#pragma unroll
    for (int q = 0; q < 4; q++) {
        float4 a = sp[lane + q * 32];
        float4 c = pp[lane + q * 32];
        float4 b = bb[lane + q * 32];
        x[q].x = a.x + c.x + b.x;
        x[q].y = a.y + c.y + b.y;
        x[q].z = a.z + c.z + b.z;
        x[q].w = a.w + c.w + b.w;
        sum   += x[q].x + x[q].y + x[q].z + x[q].w;
        sumsq += x[q].x * x[q].x + x[q].y * x[q].y + x[q].z * x[q].z + x[q].w * x[q].w;
    }
#pragma unroll
    for (int off = 16; off > 0; off >>= 1) {
        sum   += __shfl_xor_sync(0xffffffffu, sum, off);
        sumsq += __shfl_xor_sync(0xffffffffu, sumsq, off);
    }
    float mu   = sum * (1.0f / D);
    float var  = sumsq * (1.0f / D) - mu * mu;
    float rstd = rsqrtf(var + 1e-5f);

    const float4* gg = (const float4*)(ln_g + (size_t)i * D);
    const float4* be = (const float4*)(ln_b + (size_t)i * D);
    float4* op = (float4*)(out + (size_t)row * D);
#pragma unroll
    for (int q = 0; q < 4; q++) {
        float4 g = gg[lane + q * 32];
        float4 b = be[lane + q * 32];
        float4 r;
        r.x = (x[q].x - mu) * rstd * g.x + b.x;
        r.y = (x[q].y - mu) * rstd * g.y + b.y;
        r.z = (x[q].z - mu) * rstd * g.z + b.z;
        r.w = (x[q].w - mu) * rstd * g.w + b.w;
        op[lane + q * 32] = r;
    }
}

// ---------------------------------------------------------------------------
extern "C" void kernel_launch(void* const* d_in, const int* in_sizes, int n_in,
                              void* d_out, int out_size) {
    const float* s0 = (const float*)d_in[0];
    const float* s1 = (const float*)d_in[1];
    const float* s2 = (const float*)d_in[2];
    const float* pw = (const float*)d_in[3];
    const float* pb = (const float*)d_in[4];
    const float* lg = (const float*)d_in[5];
    const float* lb = (const float*)d_in[6];

    float* out     = (float*)d_out;               // [3,B,T,D]
    float* weights = out + (size_t)NMOD * BT * D; // [3,B,T,3]

    cudaFuncSetAttribute(gemm_kernel,
                         cudaFuncAttributeMaxDynamicSharedMemorySize, GEMM_SMEM);

    fusion_kernel<<<BT / 8, 256>>>(s0, s1, s2, weights);
    wconv_kernel<<<(NMOD * D * D / 4 + 255) / 256, 256>>>(pw);

    dim3 ggrid(D / 128, BT / 128, NMOD);   // (4, 256, 3)
    gemm_kernel<<<ggrid, 256, GEMM_SMEM>>>();

    ln_kernel<<<(NMOD * BT) / 8, 256>>>(s0, s1, s2, pb, lg, lb, out);
}

// round 6
// speedup vs baseline: 6.4961x; 1.8667x over previous
#include <cuda_runtime.h>
#include <cuda_fp16.h>
#include <math.h>
#include <stdint.h>

#define BT 32768      // B*T
#define D  512
#define NMOD 3

// ---------------------------------------------------------------------------
// Scratch (__device__ globals; allocation-free rule)
// ---------------------------------------------------------------------------
__device__ __align__(16) __half g_fa[(size_t)NMOD * BT * D];   // fused states fp16
__device__ __align__(16) __half g_wb[(size_t)NMOD * D * D];    // weights fp16
__device__ __align__(16) float  g_p[(size_t)NMOD * BT * D];    // x = S + p + bias

// ---------------------------------------------------------------------------
// helpers
// ---------------------------------------------------------------------------
__device__ __forceinline__ uint32_t smem_to_u32(const void* p) {
    uint32_t a;
    asm("{ .reg .u64 t; cvta.to.shared.u64 t, %1; cvt.u32.u64 %0, t; }" : "=r"(a) : "l"(p));
    return a;
}
__device__ __forceinline__ void cp16(uint32_t s, const void* g) {
    asm volatile("cp.async.cg.shared.global [%0], [%1], 16;" :: "r"(s), "l"(g) : "memory");
}
__device__ __forceinline__ void ldsm4(uint32_t* r, uint32_t addr) {
    asm volatile("ldmatrix.sync.aligned.m8n8.x4.shared.b16 {%0,%1,%2,%3}, [%4];"
                 : "=r"(r[0]), "=r"(r[1]), "=r"(r[2]), "=r"(r[3]) : "r"(addr));
}
__device__ __forceinline__ void mma16816(float* c, const uint32_t* a, const uint32_t* b) {
    asm volatile("mma.sync.aligned.m16n8k16.row.col.f32.f16.f16.f32 "
                 "{%0,%1,%2,%3}, {%4,%5,%6,%7}, {%8,%9}, {%0,%1,%2,%3};"
                 : "+f"(c[0]), "+f"(c[1]), "+f"(c[2]), "+f"(c[3])
                 : "r"(a[0]), "r"(a[1]), "r"(a[2]), "r"(a[3]), "r"(b[0]), "r"(b[1]));
}
__device__ __forceinline__ uint2 pack4h(float4 v) {
    __half2 h01 = __floats2half2_rn(v.x, v.y);
    __half2 h23 = __floats2half2_rn(v.z, v.w);
    uint2 r;
    r.x = *(uint32_t*)&h01; r.y = *(uint32_t*)&h23;
    return r;
}

// ---------------------------------------------------------------------------
// Kernel 1: fusion -> softmax weights + fused states (fp16)
// ---------------------------------------------------------------------------
__global__ void fusion_kernel(const float* __restrict__ s0,
                              const float* __restrict__ s1,
                              const float* __restrict__ s2,
                              float* __restrict__ weights_out) {
    int gwarp = (blockIdx.x * blockDim.x + threadIdx.x) >> 5;
    int lane  = threadIdx.x & 31;
    if (gwarp >= BT) return;

    const float4* p0 = (const float4*)(s0 + (size_t)gwarp * D);
    const float4* p1 = (const float4*)(s1 + (size_t)gwarp * D);
    const float4* p2 = (const float4*)(s2 + (size_t)gwarp * D);

    float4 v0[4], v1[4], v2[4];
#pragma unroll
    for (int q = 0; q < 4; q++) {
        v0[q] = p0[lane + q * 32];
        v1[q] = p1[lane + q * 32];
        v2[q] = p2[lane + q * 32];
    }
    float d[6] = {0.f, 0.f, 0.f, 0.f, 0.f, 0.f};
#pragma unroll
    for (int q = 0; q < 4; q++) {
        float4 a = v0[q], b = v1[q], c = v2[q];
        d[0] += a.x * a.x + a.y * a.y + a.z * a.z + a.w * a.w;
        d[1] += b.x * b.x + b.y * b.y + b.z * b.z + b.w * b.w;
        d[2] += c.x * c.x + c.y * c.y + c.z * c.z + c.w * c.w;
        d[3] += a.x * b.x + a.y * b.y + a.z * b.z + a.w * b.w;
        d[4] += a.x * c.x + a.y * c.y + a.z * c.z + a.w * c.w;
        d[5] += b.x * c.x + b.y * c.y + b.z * c.z + b.w * c.w;
    }
#pragma unroll
    for (int t = 0; t < 6; t++)
#pragma unroll
        for (int off = 16; off > 0; off >>= 1)
            d[t] += __shfl_xor_sync(0xffffffffu, d[t], off);

    float n0 = sqrtf(d[0]), n1 = sqrtf(d[1]), n2 = sqrtf(d[2]);
    float sim[3][3];
    sim[0][0] = d[0] / fmaxf(n0 * n0, 1e-8f) * 2.0f;
    sim[1][1] = d[1] / fmaxf(n1 * n1, 1e-8f) * 2.0f;
    sim[2][2] = d[2] / fmaxf(n2 * n2, 1e-8f) * 2.0f;
    float s01 = d[3] / fmaxf(n0 * n1, 1e-8f) * 2.0f;
    float s02 = d[4] / fmaxf(n0 * n2, 1e-8f) * 2.0f;
    float s12 = d[5] / fmaxf(n1 * n2, 1e-8f) * 2.0f;
    sim[0][1] = s01; sim[1][0] = s01;
    sim[0][2] = s02; sim[2][0] = s02;
    sim[1][2] = s12; sim[2][1] = s12;

    float w[3][3];
#pragma unroll
    for (int i = 0; i < 3; i++) {
        float m  = fmaxf(sim[i][0], fmaxf(sim[i][1], sim[i][2]));
        float e0 = expf(sim[i][0] - m);
        float e1 = expf(sim[i][1] - m);
        float e2 = expf(sim[i][2] - m);
        float inv = 1.0f / (e0 + e1 + e2);
        w[i][0] = e0 * inv; w[i][1] = e1 * inv; w[i][2] = e2 * inv;
    }
    if (lane < 9) {
        int i = lane / 3, j = lane % 3;
        weights_out[((size_t)i * BT + gwarp) * 3 + j] = w[i][j];
    }
#pragma unroll
    for (int i = 0; i < 3; i++) {
        uint2* dst = (uint2*)(g_fa + ((size_t)i * BT + gwarp) * D);
        float w0 = w[i][0], w1 = w[i][1], w2 = w[i][2];
#pragma unroll
        for (int q = 0; q < 4; q++) {
            float4 r;
            r.x = w0 * v0[q].x + w1 * v1[q].x + w2 * v2[q].x;
            r.y = w0 * v0[q].y + w1 * v1[q].y + w2 * v2[q].y;
            r.z = w0 * v0[q].z + w1 * v1[q].z + w2 * v2[q].z;
            r.w = w0 * v0[q].w + w1 * v1[q].w + w2 * v2[q].w;
            dst[lane + q * 32] = pack4h(r);
        }
    }
}

// ---------------------------------------------------------------------------
// Kernel 1b: convert proj_w (fp32) -> fp16
// ---------------------------------------------------------------------------
__global__ void wconv_kernel(const float* __restrict__ pw) {
    int idx = blockIdx.x * blockDim.x + threadIdx.x;
    const int total = NMOD * D * D / 4;
    if (idx >= total) return;
    float4 v = ((const float4*)pw)[idx];
    ((uint2*)g_wb)[idx] = pack4h(v);
}

// ---------------------------------------------------------------------------
// Kernel 2: fp16 mma.sync GEMM (single pass), fp32 accum.
// CTA tile 128x128, warp tile 32x64, K chunk 32, double-buffered cp.async.
// SMEM rows padded to 40 halves (80B). Epilogue: x = acc + bias + S -> g_p.
// ---------------------------------------------------------------------------
#define CHUNK_B   20480              // one buffer: 2 arrays * 128 rows * 80B
#define A_OFF     0
#define B_OFF     10240
#define GEMM_SMEM (2 * CHUNK_B)      // 40960

__global__ void __launch_bounds__(256, 2)
gemm_kernel(const float* __restrict__ s0,
            const float* __restrict__ s1,
            const float* __restrict__ s2,
            const float* __restrict__ proj_b) {
    extern __shared__ char sm[];
    const uint32_t smb = smem_to_u32(sm);
    const int tid  = threadIdx.x;
    const int wid  = tid >> 5;
    const int lane = tid & 31;
    const int n0   = blockIdx.x * 128;
    const int m0   = blockIdx.y * 128;
    const int mod  = blockIdx.z;

    const int wr = wid & 3;        // warp row (32 m-rows each)
    const int wc = wid >> 2;       // warp col (64 n-cols each)

    const uint4* ga = (const uint4*)(g_fa + (size_t)mod * BT * D);
    const uint4* gb = (const uint4*)(g_wb + (size_t)mod * D * D);
    // global row stride = 512 halves = 64 uint4

    auto load_chunk = [&](int ch, int buf) {
        const uint32_t bb = smb + buf * CHUNK_B;
#pragma unroll
        for (int it = 0; it < 2; it++) {
            int idx = tid + it * 256;        // 0..511
            int row = idx >> 2;              // 0..127
            int pc  = idx & 3;               // 16B piece (32 halves per chunk row)
            uint32_t so = bb + row * 80 + pc * 16;
            size_t gaidx = (size_t)(m0 + row) * 64 + ch * 4 + pc;
            size_t gbidx = (size_t)(n0 + row) * 64 + ch * 4 + pc;
            cp16(so + A_OFF, ga + gaidx);
            cp16(so + B_OFF, gb + gbidx);
        }
        asm volatile("cp.async.commit_group;" ::: "memory");
    };

    float acc[2][8][4];
#pragma unroll
    for (int mt = 0; mt < 2; mt++)
#pragma unroll
        for (int nt = 0; nt < 8; nt++)
#pragma unroll
            for (int q = 0; q < 4; q++) acc[mt][nt][q] = 0.f;

    const uint32_t a_row = wr * 32 + (lane & 15);
    const uint32_t a_col = (lane >> 4) << 3;
    const uint32_t b_row = wc * 64 + (((lane >> 4) << 3) | (lane & 7));
    const uint32_t b_col = ((lane >> 3) & 1) << 3;

    load_chunk(0, 0);

    for (int ch = 0; ch < 16; ch++) {
        if (ch < 15) {
            load_chunk(ch + 1, (ch + 1) & 1);
            asm volatile("cp.async.wait_group 1;" ::: "memory");
        } else {
            asm volatile("cp.async.wait_group 0;" ::: "memory");
        }
        __syncthreads();

        const uint32_t bb = smb + (ch & 1) * CHUNK_B;
#pragma unroll
        for (int kk2 = 0; kk2 < 2; kk2++) {
            const uint32_t kk = kk2 * 16;
            uint32_t a[2][4];
#pragma unroll
            for (int mt = 0; mt < 2; mt++)
                ldsm4(a[mt], bb + A_OFF + (a_row + mt * 16) * 80 + (a_col + kk) * 2);
            uint32_t b[4][4];
#pragma unroll
            for (int np = 0; np < 4; np++)
                ldsm4(b[np], bb + B_OFF + (b_row + np * 16) * 80 + (b_col + kk) * 2);
#pragma unroll
            for (int mt = 0; mt < 2; mt++)
#pragma unroll
                for (int nt = 0; nt < 8; nt++)
                    mma16816(acc[mt][nt], a[mt], &b[nt >> 1][(nt & 1) * 2]);
        }
        __syncthreads();
    }

    // epilogue: x = acc + bias + S -> g_p
    const float* Sb = (mod == 0) ? s0 : ((mod == 1) ? s1 : s2);
    const float* pbm = proj_b + (size_t)mod * D;
    float* Cp = g_p + (size_t)mod * BT * D;
    const int gid = lane >> 2, tq = lane & 3;
#pragma unroll
    for (int mt = 0; mt < 2; mt++) {
        const int r0 = m0 + wr * 32 + mt * 16 + gid;
#pragma unroll
        for (int nt = 0; nt < 8; nt++) {
            const int c = n0 + wc * 64 + nt * 8 + tq * 2;
            float2 bv  = *(const float2*)(pbm + c);
            float2 sv0 = *(const float2*)(Sb + (size_t)r0 * D + c);
            float2 sv1 = *(const float2*)(Sb + (size_t)(r0 + 8) * D + c);
            *(float2*)(Cp + (size_t)r0 * D + c) =
                make_float2(acc[mt][nt][0] + bv.x + sv0.x, acc[mt][nt][1] + bv.y + sv0.y);
            *(float2*)(Cp + (size_t)(r0 + 8) * D + c) =
                make_float2(acc[mt][nt][2] + bv.x + sv1.x, acc[mt][nt][3] + bv.y + sv1.y);
        }
    }
}

// ---------------------------------------------------------------------------
// Kernel 3: LayerNorm over precomputed x in g_p; write out.
// ---------------------------------------------------------------------------
__global__ void ln_kernel(const float* __restrict__ ln_g,
                          const float* __restrict__ ln_b,
                          float* __restrict__ out) {
    int row  = (blockIdx.x * blockDim.x + threadIdx.x) >> 5;
    int lane = threadIdx.x & 31;
    if (row >= NMOD * BT) return;
    int i = row / BT;

    const float4* pp = (const float4*)(g_p + (size_t)row * D);

    float4 x[4];
    float sum = 0.f, sumsq = 0.f;
#pragma unroll
    for (int q = 0; q < 4; q++) {
        x[q] = pp[lane + q * 32];
        sum   += x[q].x + x[q].y + x[q].z + x[q].w;
        sumsq += x[q].x * x[q].x + x[q].y * x[q].y + x[q].z * x[q].z + x[q].w * x[q].w;
    }
#pragma unroll
    for (int off = 16; off > 0; off >>= 1) {
        sum   += __shfl_xor_sync(0xffffffffu, sum, off);
        sumsq += __shfl_xor_sync(0xffffffffu, sumsq, off);
    }
    float mu   = sum * (1.0f / D);
    float var  = sumsq * (1.0f / D) - mu * mu;
    float rstd = rsqrtf(var + 1e-5f);

    const float4* gg = (const float4*)(ln_g + (size_t)i * D);
    const float4* be = (const float4*)(ln_b + (size_t)i * D);
    float4* op = (float4*)(out + (size_t)row * D);
#pragma unroll
    for (int q = 0; q < 4; q++) {
        float4 g = gg[lane + q * 32];
        float4 b = be[lane + q * 32];
        float4 r;
        r.x = (x[q].x - mu) * rstd * g.x + b.x;
        r.y = (x[q].y - mu) * rstd * g.y + b.y;
        r.z = (x[q].z - mu) * rstd * g.z + b.z;
        r.w = (x[q].w - mu) * rstd * g.w + b.w;
        op[lane + q * 32] = r;
    }
}

// ---------------------------------------------------------------------------
extern "C" void kernel_launch(void* const* d_in, const int* in_sizes, int n_in,
                              void* d_out, int out_size) {
    const float* s0 = (const float*)d_in[0];
    const float* s1 = (const float*)d_in[1];
    const float* s2 = (const float*)d_in[2];
    const float* pw = (const float*)d_in[3];
    const float* pb = (const float*)d_in[4];
    const float* lg = (const float*)d_in[5];
    const float* lb = (const float*)d_in[6];

    float* out     = (float*)d_out;               // [3,B,T,D]
    float* weights = out + (size_t)NMOD * BT * D; // [3,B,T,3]

    cudaFuncSetAttribute(gemm_kernel,
                         cudaFuncAttributeMaxDynamicSharedMemorySize, GEMM_SMEM);

    fusion_kernel<<<BT / 8, 256>>>(s0, s1, s2, weights);
    wconv_kernel<<<(NMOD * D * D / 4 + 255) / 256, 256>>>(pw);

    dim3 ggrid(D / 128, BT / 128, NMOD);   // (4, 256, 3)
    gemm_kernel<<<ggrid, 256, GEMM_SMEM>>>(s0, s1, s2, pb);

    ln_kernel<<<(NMOD * BT) / 8, 256>>>(lg, lb, out);
}